// round 9
// baseline (speedup 1.0000x reference)
#include <cuda_runtime.h>

#define BB 2
#define NF 16
#define NG 4               // channel groups of 4 (float4)
#define HH 512
#define WW 512
#define H2 1024
#define W2 1024
#define CINc 50
#define HW (HH*WW)
#define HW2 (H2*W2)

// warp/combine tiles: 16x16 outputs at 512-res
#define TSW 16
#define TWW 34             // 2*TSW+2
#define TWNW (TWW*TWW)     // 1156
#define NPOS 5             // ceil(TWNW/256)

// conv strip height
#define CR 4

// -------- scratch (device globals; referenced ONLY from device code) --------
__device__ float4 g_up16 [(size_t)BB*NG*HW2];  // upsampled tgt, channel-packed x4
__device__ float  g_warped[(size_t)BB*NF*HW];  // warped tgt @512, planar
__device__ float  g_adj  [(size_t)BB*2*HW];    // conv output, planar
__device__ float  g_newres[(size_t)BB*2*HW];   // combined residual, planar
__device__ float2 g_a1024[(size_t)BB*HW2];     // up(res)*2, interleaved
__device__ float2 g_b1024[(size_t)BB*HW2];     // up(adj)*2
__device__ float2 g_nr1024[(size_t)BB*HW2];    // up(new_res)*2

// -------- resize helpers (jax.image.resize bilinear; validated R1) --------
__device__ __forceinline__ void up_taps(int i, int n_in, int& t0, int& t1,
                                        float& w0, float& w1) {
    int k = i >> 1;
    if ((i & 1) == 0) { t0 = k - 1; t1 = k;     w0 = 0.25f; w1 = 0.75f; }
    else              { t0 = k;     t1 = k + 1; w0 = 0.75f; w1 = 0.25f; }
    if (t0 < 0)     { t0 = t1; w0 = 0.f; w1 = 1.f; }
    if (t1 >= n_in) { t1 = t0; w1 = 0.f; w0 = 1.f; }
}
__device__ __forceinline__ float dbase(int t) { return (t == 0 || t == 3) ? 0.25f : 0.75f; }

// -------- kernel 1: upsample tgt 512->1024 into channel-packed float4 --------
__global__ void __launch_bounds__(256) k_up_img(const float* __restrict__ x) {
    int idx = blockIdx.x * blockDim.x + threadIdx.x;
    if (idx >= BB * HW2) return;
    int xx = idx & (W2 - 1), yy = (idx >> 10) & (H2 - 1), b = idx >> 20;
    int ty0, ty1, tx0, tx1; float wy0, wy1, wx0, wx1;
    up_taps(yy, HH, ty0, ty1, wy0, wy1);
    up_taps(xx, WW, tx0, tx1, wx0, wx1);
    int r0 = ty0 * WW, r1 = ty1 * WW;
    float w00 = wy0 * wx0, w01 = wy0 * wx1, w10 = wy1 * wx0, w11 = wy1 * wx1;

    const float* xb = x + ((size_t)b * 2 * NF + NF) * HW;
    float4* ob = g_up16 + (size_t)b * NG * HW2 + (size_t)yy * W2 + xx;
    #pragma unroll
    for (int g = 0; g < NG; g++) {
        float4 o;
        float* oo = (float*)&o;
        #pragma unroll
        for (int j = 0; j < 4; j++) {
            const float* p = xb + (size_t)(4 * g + j) * HW;
            oo[j] = w00 * p[r0 + tx0] + w01 * p[r0 + tx1]
                  + w10 * p[r1 + tx0] + w11 * p[r1 + tx1];
        }
        ob[(size_t)g * HW2] = o;
    }
}

// -------- kernel 2: upsample a 2ch 512 field ->1024, *2, interleaved float2 ----
__global__ void __launch_bounds__(256) k_up_res(const float* __restrict__ ext,
                                                int src_sel, int dst_sel) {
    int idx = blockIdx.x * blockDim.x + threadIdx.x;
    if (idx >= BB * H2 * (W2 / 4)) return;
    int xq = idx & (W2 / 4 - 1);
    int yy = (idx >> 8) & (H2 - 1);
    int b  = idx >> 18;
    int m = 2 * xq;
    int mm1 = max(m - 1, 0), mp2 = min(m + 2, WW - 1);
    float a00 = (m == 0) ? 0.f : 0.25f,  a01 = (m == 0) ? 1.f : 0.75f;
    float a30 = (m == WW - 2) ? 1.f : 0.75f, a31 = (m == WW - 2) ? 0.f : 0.25f;
    int ty0, ty1; float wy0, wy1;
    up_taps(yy, HH, ty0, ty1, wy0, wy1);
    int r0 = ty0 * WW, r1 = ty1 * WW;

    const float* src = (src_sel == 0) ? ext : ((src_sel == 1) ? g_adj : g_newres);
    const float* p0 = src + (size_t)b * 2 * HW;
    const float* p1 = p0 + HW;
    float ox[4], oy[4];
    {
        float s0 = p0[r0 + mm1]   * wy0 + p0[r1 + mm1]   * wy1;
        float s1 = p0[r0 + m]     * wy0 + p0[r1 + m]     * wy1;
        float s2 = p0[r0 + m + 1] * wy0 + p0[r1 + m + 1] * wy1;
        float s3 = p0[r0 + mp2]   * wy0 + p0[r1 + mp2]   * wy1;
        ox[0] = a00 * s0 + a01 * s1;  ox[1] = 0.75f * s1 + 0.25f * s2;
        ox[2] = 0.25f * s1 + 0.75f * s2;  ox[3] = a30 * s2 + a31 * s3;
    }
    {
        float s0 = p1[r0 + mm1]   * wy0 + p1[r1 + mm1]   * wy1;
        float s1 = p1[r0 + m]     * wy0 + p1[r1 + m]     * wy1;
        float s2 = p1[r0 + m + 1] * wy0 + p1[r1 + m + 1] * wy1;
        float s3 = p1[r0 + mp2]   * wy0 + p1[r1 + mp2]   * wy1;
        oy[0] = a00 * s0 + a01 * s1;  oy[1] = 0.75f * s1 + 0.25f * s2;
        oy[2] = 0.25f * s1 + 0.75f * s2;  oy[3] = a30 * s2 + a31 * s3;
    }
    float2* dst = (dst_sel == 0) ? g_a1024 : ((dst_sel == 1) ? g_b1024 : g_nr1024);
    float4* ob = (float4*)(dst + (size_t)b * HW2 + (size_t)yy * W2 + 4 * xq);
    ob[0] = make_float4(2.f * ox[0], 2.f * oy[0], 2.f * ox[1], 2.f * oy[1]);
    ob[1] = make_float4(2.f * ox[2], 2.f * oy[2], 2.f * ox[3], 2.f * oy[3]);
}

// -------- fused: reg gather tables -> 4ch-at-a-time warp+downsample --------
__global__ void __launch_bounds__(256) k_warpdown(
        float* __restrict__ out, int field_sel, int to_final) {
    __shared__ float4 s_w[TWNW];
    int b = blockIdx.z;
    int x0 = blockIdx.x * TSW, y0 = blockIdx.y * TSW;
    int gx0 = 2 * x0 - 1, gy0 = 2 * y0 - 1;
    int tid = threadIdx.x;

    const float2* fld = ((field_sel == 0) ? g_a1024 : g_nr1024) + (size_t)b * HW2;

    float4   rw[NPOS];
    unsigned rpk[NPOS];
    #pragma unroll
    for (int k = 0; k < NPOS; k++) {
        int i = tid + 256 * k;
        if (i < TWNW) {
            int r = i / TWW, cc = i - r * TWW;
            int Y = min(max(gy0 + r, 0), H2 - 1);
            int X = min(max(gx0 + cc, 0), W2 - 1);
            float2 f = fld[Y * W2 + X];
            float sx = (float)(gx0 + cc) + f.x;
            float sy = (float)(gy0 + r) + f.y;
            float xf = floorf(sx), yf = floorf(sy);
            float fx = sx - xf, fy = sy - yf;
            int ix0 = (int)xf, iy0 = (int)yf;
            bool bx0 = (unsigned)ix0 < W2, bx1 = (unsigned)(ix0 + 1) < W2;
            bool by0 = (unsigned)iy0 < H2, by1 = (unsigned)(iy0 + 1) < H2;
            float wx0 = bx0 ? (1.f - fx) : 0.f, wx1 = bx1 ? fx : 0.f;
            float wy0 = by0 ? (1.f - fy) : 0.f, wy1 = by1 ? fy : 0.f;
            rw[k] = make_float4(wy0 * wx0, wy0 * wx1, wy1 * wx0, wy1 * wx1);
            int cx0 = min(max(ix0, 0), W2 - 1), cx1 = min(max(ix0 + 1, 0), W2 - 1);
            int cy0 = min(max(iy0, 0), H2 - 1), cy1 = min(max(iy0 + 1, 0), H2 - 1);
            rpk[k] = (unsigned)(cy0 * W2 + cx0)
                   | ((unsigned)(cx1 - cx0) << 20)
                   | ((unsigned)(cy1 - cy0) << 21);
        }
    }

    const float4* img = g_up16 + (size_t)b * NG * HW2;
    float* dstb = to_final ? (out + ((size_t)b * 2 * NF + NF) * HW)
                           : (g_warped + (size_t)b * NF * HW);
    int lx = tid & (TSW - 1), ly = tid >> 4;
    int yy = y0 + ly, xx = x0 + lx;
    float invsy = (yy == 0 || yy == HH - 1) ? (1.f / 1.75f) : 0.5f;
    float invsx = (xx == 0 || xx == WW - 1) ? (1.f / 1.75f) : 0.5f;
    float wyv[4], wxv[4];
    #pragma unroll
    for (int t = 0; t < 4; t++) {
        wyv[t] = ((unsigned)(gy0 + 2 * ly + t) < H2) ? dbase(t) * invsy : 0.f;
        wxv[t] = ((unsigned)(gx0 + 2 * lx + t) < W2) ? dbase(t) * invsx : 0.f;
    }
    int sbase = (2 * ly) * TWW + 2 * lx;
    int opix = yy * WW + xx;

    for (int g = 0; g < NG; g++) {
        const float4* p = img + (size_t)g * HW2;
        #pragma unroll
        for (int k = 0; k < NPOS; k++) {
            int i = tid + 256 * k;
            if (i < TWNW) {
                unsigned pk = rpk[k];
                float4 w = rw[k];
                int o00 = (int)(pk & 0xFFFFFu);
                int dx  = (int)((pk >> 20) & 1u);
                int o10 = o00 + (int)((pk >> 11) & 1024u);
                float4 v00 = p[o00], v01 = p[o00 + dx];
                float4 v10 = p[o10], v11 = p[o10 + dx];
                float4 acc;
                acc.x = w.x * v00.x + w.y * v01.x + w.z * v10.x + w.w * v11.x;
                acc.y = w.x * v00.y + w.y * v01.y + w.z * v10.y + w.w * v11.y;
                acc.z = w.x * v00.z + w.y * v01.z + w.z * v10.z + w.w * v11.z;
                acc.w = w.x * v00.w + w.y * v01.w + w.z * v10.w + w.w * v11.w;
                s_w[i] = acc;
            }
        }
        __syncthreads();
        float4 acc = make_float4(0.f, 0.f, 0.f, 0.f);
        #pragma unroll
        for (int ty = 0; ty < 4; ty++) {
            const float4* sr = s_w + sbase + ty * TWW;
            float4 rowv = make_float4(0.f, 0.f, 0.f, 0.f);
            #pragma unroll
            for (int tx = 0; tx < 4; tx++) {
                float4 v = sr[tx];
                float w = wxv[tx];
                rowv.x += w * v.x; rowv.y += w * v.y;
                rowv.z += w * v.z; rowv.w += w * v.w;
            }
            float w = wyv[ty];
            acc.x += w * rowv.x; acc.y += w * rowv.y;
            acc.z += w * rowv.z; acc.w += w * rowv.w;
        }
        dstb[(size_t)(4 * g + 0) * HW + opix] = acc.x;
        dstb[(size_t)(4 * g + 1) * HW + opix] = acc.y;
        dstb[(size_t)(4 * g + 2) * HW + opix] = acc.z;
        dstb[(size_t)(4 * g + 3) * HW + opix] = acc.w;
        __syncthreads();
    }
}

// -------- 3x3 conv 50->2: CR-row strip, rolling register window --------------
__global__ void __launch_bounds__(256) k_conv(
        const float* __restrict__ x, const float* __restrict__ res,
        const float* __restrict__ Wc, const float* __restrict__ bias,
        float* __restrict__ out) {
    __shared__ float sw[2 * CINc * 9];
    for (int i = threadIdx.x; i < 2 * CINc * 9; i += blockDim.x) sw[i] = Wc[i];
    __syncthreads();
    int idx = blockIdx.x * blockDim.x + threadIdx.x;
    if (idx >= BB * (HH / CR) * WW) return;
    int xx = idx & (WW - 1);
    int ys = (idx >> 9) & (HH / CR - 1);
    int b  = idx >> (9 + 7);      // 9 bits x, 7 bits ys (HH/CR=128)
    int y0 = ys * CR;

    const float* xb = x + (size_t)b * 2 * NF * HW;
    const float* wb = g_warped + (size_t)b * NF * HW;
    const float* rb = res + (size_t)b * 2 * HW;
    bool lok = (xx > 0), rok = (xx < WW - 1);

    float a0[CR], a1[CR];
    #pragma unroll
    for (int k = 0; k < CR; k++) { a0[k] = 0.f; a1[k] = 0.f; }

    // macro-free channel loop over three planar sources (no per-c select)
    #pragma unroll 1
    for (int seg = 0; seg < 3; seg++) {
        const float* base = (seg == 0) ? xb : ((seg == 1) ? wb : rb);
        int c0   = (seg == 0) ? 0  : ((seg == 1) ? 32 : 48);
        int cend = (seg == 0) ? 32 : ((seg == 1) ? 48 : 50);
        #pragma unroll 1
        for (int c = c0; c < cend; c++) {
            const float* p = base + (size_t)(c - c0) * HW;
            const float* q = sw + c * 9;
            const float* u = sw + CINc * 9 + c * 9;
            float q0 = q[0], q1 = q[1], q2 = q[2], q3 = q[3], q4 = q[4];
            float q5 = q[5], q6 = q[6], q7 = q[7], q8 = q[8];
            float u0 = u[0], u1 = u[1], u2 = u[2], u3 = u[3], u4 = u[4];
            float u5 = u[5], u6 = u[6], u7 = u[7], u8 = u[8];

            float vm[3], v0[3], vp[3];
            #pragma unroll
            for (int r = 0; r < CR + 2; r++) {
                int yr = y0 - 1 + r;
                int slot = r % 3;
                if ((unsigned)yr < HH) {
                    int ro = yr * WW + xx;
                    vm[slot] = lok ? p[ro - 1] : 0.f;
                    v0[slot] = p[ro];
                    vp[slot] = rok ? p[ro + 1] : 0.f;
                } else {
                    vm[slot] = 0.f; v0[slot] = 0.f; vp[slot] = 0.f;
                }
                if (r >= 2) {
                    int k = r - 2;
                    int st = (r - 2) % 3, sm = (r - 1) % 3, sb = r % 3;
                    a0[k] += vm[st] * q0 + v0[st] * q1 + vp[st] * q2
                           + vm[sm] * q3 + v0[sm] * q4 + vp[sm] * q5
                           + vm[sb] * q6 + v0[sb] * q7 + vp[sb] * q8;
                    a1[k] += vm[st] * u0 + v0[st] * u1 + vp[st] * u2
                           + vm[sm] * u3 + v0[sm] * u4 + vp[sm] * u5
                           + vm[sb] * u6 + v0[sb] * u7 + vp[sb] * u8;
                }
            }
        }
    }

    float b0 = bias[0], b1 = bias[1];
    float* o = g_adj + (size_t)b * 2 * HW;
    #pragma unroll
    for (int k = 0; k < CR; k++) {
        int pc = (y0 + k) * WW + xx;
        o[pc]      = a0[k] + b0;
        o[HW + pc] = a1[k] + b1;
    }
    // pass-through: out[b][0..15] = x[b][0..15]
    float* ob = out + (size_t)b * 2 * NF * HW;
    #pragma unroll
    for (int c = 0; c < NF; c++) {
        const float* ps = xb + (size_t)c * HW;
        float* pd = ob + (size_t)c * HW;
        #pragma unroll
        for (int k = 0; k < CR; k++) {
            int pc = (y0 + k) * WW + xx;
            pd[pc] = ps[pc];
        }
    }
}

// -------- fused: warp a1024 by b1024 (tables) -> downsample*0.5 + adj ----------
__global__ void __launch_bounds__(256) k_combine() {
    __shared__ float2 s_w[TWNW];
    int b = blockIdx.z;
    int x0 = blockIdx.x * TSW, y0 = blockIdx.y * TSW;
    int gx0 = 2 * x0 - 1, gy0 = 2 * y0 - 1;
    int tid = threadIdx.x;

    const float2* bf = g_b1024 + (size_t)b * HW2;
    const float2* af = g_a1024 + (size_t)b * HW2;

    #pragma unroll
    for (int k = 0; k < NPOS; k++) {
        int i = tid + 256 * k;
        if (i < TWNW) {
            int r = i / TWW, cc = i - r * TWW;
            int Y = min(max(gy0 + r, 0), H2 - 1);
            int X = min(max(gx0 + cc, 0), W2 - 1);
            float2 f = bf[Y * W2 + X];
            float sx = (float)(gx0 + cc) + f.x;
            float sy = (float)(gy0 + r) + f.y;
            float xf = floorf(sx), yf = floorf(sy);
            float fx = sx - xf, fy = sy - yf;
            int ix0 = (int)xf, iy0 = (int)yf;
            bool bx0 = (unsigned)ix0 < W2, bx1 = (unsigned)(ix0 + 1) < W2;
            bool by0 = (unsigned)iy0 < H2, by1 = (unsigned)(iy0 + 1) < H2;
            float wx0 = bx0 ? (1.f - fx) : 0.f, wx1 = bx1 ? fx : 0.f;
            float wy0 = by0 ? (1.f - fy) : 0.f, wy1 = by1 ? fy : 0.f;
            float w00 = wy0 * wx0, w01 = wy0 * wx1, w10 = wy1 * wx0, w11 = wy1 * wx1;
            int cx0 = min(max(ix0, 0), W2 - 1), cx1 = min(max(ix0 + 1, 0), W2 - 1);
            int cy0 = min(max(iy0, 0), H2 - 1), cy1 = min(max(iy0 + 1, 0), H2 - 1);
            int o00 = cy0 * W2 + cx0;
            int dxo = cx1 - cx0;
            int o10 = o00 + (cy1 - cy0) * W2;
            float2 v00 = af[o00], v01 = af[o00 + dxo];
            float2 v10 = af[o10], v11 = af[o10 + dxo];
            s_w[i] = make_float2(
                w00 * v00.x + w01 * v01.x + w10 * v10.x + w11 * v11.x,
                w00 * v00.y + w01 * v01.y + w10 * v10.y + w11 * v11.y);
        }
    }
    __syncthreads();

    int lx = tid & (TSW - 1), ly = tid >> 4;
    int yy = y0 + ly, xx = x0 + lx;
    float invsy = (yy == 0 || yy == HH - 1) ? (1.f / 1.75f) : 0.5f;
    float invsx = (xx == 0 || xx == WW - 1) ? (1.f / 1.75f) : 0.5f;
    float wyv[4], wxv[4];
    #pragma unroll
    for (int t = 0; t < 4; t++) {
        wyv[t] = ((unsigned)(gy0 + 2 * ly + t) < H2) ? dbase(t) * invsy : 0.f;
        wxv[t] = ((unsigned)(gx0 + 2 * lx + t) < W2) ? dbase(t) * invsx : 0.f;
    }
    int sbase = (2 * ly) * TWW + 2 * lx;
    float accx = 0.f, accy = 0.f;
    #pragma unroll
    for (int ty = 0; ty < 4; ty++) {
        const float2* sr = s_w + sbase + ty * TWW;
        float rx = wxv[0] * sr[0].x + wxv[1] * sr[1].x + wxv[2] * sr[2].x + wxv[3] * sr[3].x;
        float ry = wxv[0] * sr[0].y + wxv[1] * sr[1].y + wxv[2] * sr[2].y + wxv[3] * sr[3].y;
        accx += wyv[ty] * rx;
        accy += wyv[ty] * ry;
    }
    int p = yy * WW + xx;
    const float* ad = g_adj + (size_t)b * 2 * HW;
    float* nr = g_newres + (size_t)b * 2 * HW;
    nr[p]      = ad[p]      + 0.5f * accx;
    nr[HW + p] = ad[HW + p] + 0.5f * accy;
}

// -------- launch --------
extern "C" void kernel_launch(void* const* d_in, const int* in_sizes, int n_in,
                              void* d_out, int out_size) {
    const float* x    = (const float*)d_in[0];
    const float* res  = (const float*)d_in[1];
    const float* Wc   = (const float*)d_in[2];
    const float* bias = (const float*)d_in[3];
    float* out = (float*)d_out;

    const int T = 256;
    dim3 gu1((BB * HW2 + T - 1) / T);
    dim3 gu((BB * H2 * (W2 / 4) + T - 1) / T);
    dim3 gcv((BB * (HH / CR) * WW + T - 1) / T);
    dim3 gw(HH / TSW, WW / TSW, BB);

    k_up_img<<<gu1, T>>>(x);                      // tgt -> g_up16 (packed x4)
    k_up_res<<<gu, T>>>(res, 0, 0);               // res -> g_a1024 (*2)
    k_warpdown<<<gw, T>>>(nullptr, 0, 0);         // warp by a1024 -> g_warped
    k_conv<<<gcv, T>>>(x, res, Wc, bias, out);    // adj + src pass-through
    k_up_res<<<gu, T>>>(nullptr, 1, 1);           // adj -> g_b1024 (*2)
    k_combine<<<gw, T>>>();                       // -> g_newres
    k_up_res<<<gu, T>>>(nullptr, 2, 2);           // new_res -> g_nr1024 (*2)
    k_warpdown<<<gw, T>>>(out, 1, 1);             // warp by nr1024 -> out[16..31]
}

// round 10
// speedup vs baseline: 1.0509x; 1.0509x over previous
#include <cuda_runtime.h>

#define BB 2
#define NF 16
#define NG 4               // channel groups of 4 (float4)
#define HH 512
#define WW 512
#define H2 1024
#define W2 1024
#define CINc 50
#define HW (HH*WW)
#define HW2 (H2*W2)

// warp/combine tiles: 16x16 outputs at 512-res
#define TSW 16
#define TWW 34             // 2*TSW+2
#define TWNW (TWW*TWW)     // 1156
#define NPOS 5             // ceil(TWNW/256)

// conv tile
#define CTS 32             // 32x32 outputs per block
#define CTW 34             // with halo
#define CTP 36             // padded smem row stride (bank-conflict-free)

// -------- scratch (device globals; referenced ONLY from device code) --------
__device__ float4 g_up16 [(size_t)BB*NG*HW2];  // upsampled tgt, channel-packed x4
__device__ float  g_warped[(size_t)BB*NF*HW];  // warped tgt @512, planar
__device__ float  g_adj  [(size_t)BB*2*HW];    // conv output, planar
__device__ float  g_newres[(size_t)BB*2*HW];   // combined residual, planar
__device__ float2 g_a1024[(size_t)BB*HW2];     // up(res)*2, interleaved
__device__ float2 g_b1024[(size_t)BB*HW2];     // up(adj)*2
__device__ float2 g_nr1024[(size_t)BB*HW2];    // up(new_res)*2

// -------- resize helpers (jax.image.resize bilinear; validated R1) --------
__device__ __forceinline__ void up_taps(int i, int n_in, int& t0, int& t1,
                                        float& w0, float& w1) {
    int k = i >> 1;
    if ((i & 1) == 0) { t0 = k - 1; t1 = k;     w0 = 0.25f; w1 = 0.75f; }
    else              { t0 = k;     t1 = k + 1; w0 = 0.75f; w1 = 0.25f; }
    if (t0 < 0)     { t0 = t1; w0 = 0.f; w1 = 1.f; }
    if (t1 >= n_in) { t1 = t0; w1 = 0.f; w0 = 1.f; }
}
__device__ __forceinline__ float dbase(int t) { return (t == 0 || t == 3) ? 0.25f : 0.75f; }

// -------- kernel 1: upsample tgt 512->1024 into channel-packed float4 --------
__global__ void __launch_bounds__(256) k_up_img(const float* __restrict__ x) {
    int idx = blockIdx.x * blockDim.x + threadIdx.x;
    if (idx >= BB * HW2) return;
    int xx = idx & (W2 - 1), yy = (idx >> 10) & (H2 - 1), b = idx >> 20;
    int ty0, ty1, tx0, tx1; float wy0, wy1, wx0, wx1;
    up_taps(yy, HH, ty0, ty1, wy0, wy1);
    up_taps(xx, WW, tx0, tx1, wx0, wx1);
    int r0 = ty0 * WW, r1 = ty1 * WW;
    float w00 = wy0 * wx0, w01 = wy0 * wx1, w10 = wy1 * wx0, w11 = wy1 * wx1;

    const float* xb = x + ((size_t)b * 2 * NF + NF) * HW;
    float4* ob = g_up16 + (size_t)b * NG * HW2 + (size_t)yy * W2 + xx;
    #pragma unroll
    for (int g = 0; g < NG; g++) {
        float4 o;
        float* oo = (float*)&o;
        #pragma unroll
        for (int j = 0; j < 4; j++) {
            const float* p = xb + (size_t)(4 * g + j) * HW;
            oo[j] = w00 * p[r0 + tx0] + w01 * p[r0 + tx1]
                  + w10 * p[r1 + tx0] + w11 * p[r1 + tx1];
        }
        ob[(size_t)g * HW2] = o;
    }
}

// -------- kernel 2: upsample a 2ch 512 field ->1024, *2, interleaved float2 ----
__global__ void __launch_bounds__(256) k_up_res(const float* __restrict__ ext,
                                                int src_sel, int dst_sel) {
    int idx = blockIdx.x * blockDim.x + threadIdx.x;
    if (idx >= BB * H2 * (W2 / 4)) return;
    int xq = idx & (W2 / 4 - 1);
    int yy = (idx >> 8) & (H2 - 1);
    int b  = idx >> 18;
    int m = 2 * xq;
    int mm1 = max(m - 1, 0), mp2 = min(m + 2, WW - 1);
    float a00 = (m == 0) ? 0.f : 0.25f,  a01 = (m == 0) ? 1.f : 0.75f;
    float a30 = (m == WW - 2) ? 1.f : 0.75f, a31 = (m == WW - 2) ? 0.f : 0.25f;
    int ty0, ty1; float wy0, wy1;
    up_taps(yy, HH, ty0, ty1, wy0, wy1);
    int r0 = ty0 * WW, r1 = ty1 * WW;

    const float* src = (src_sel == 0) ? ext : ((src_sel == 1) ? g_adj : g_newres);
    const float* p0 = src + (size_t)b * 2 * HW;
    const float* p1 = p0 + HW;
    float ox[4], oy[4];
    {
        float s0 = p0[r0 + mm1]   * wy0 + p0[r1 + mm1]   * wy1;
        float s1 = p0[r0 + m]     * wy0 + p0[r1 + m]     * wy1;
        float s2 = p0[r0 + m + 1] * wy0 + p0[r1 + m + 1] * wy1;
        float s3 = p0[r0 + mp2]   * wy0 + p0[r1 + mp2]   * wy1;
        ox[0] = a00 * s0 + a01 * s1;  ox[1] = 0.75f * s1 + 0.25f * s2;
        ox[2] = 0.25f * s1 + 0.75f * s2;  ox[3] = a30 * s2 + a31 * s3;
    }
    {
        float s0 = p1[r0 + mm1]   * wy0 + p1[r1 + mm1]   * wy1;
        float s1 = p1[r0 + m]     * wy0 + p1[r1 + m]     * wy1;
        float s2 = p1[r0 + m + 1] * wy0 + p1[r1 + m + 1] * wy1;
        float s3 = p1[r0 + mp2]   * wy0 + p1[r1 + mp2]   * wy1;
        oy[0] = a00 * s0 + a01 * s1;  oy[1] = 0.75f * s1 + 0.25f * s2;
        oy[2] = 0.25f * s1 + 0.75f * s2;  oy[3] = a30 * s2 + a31 * s3;
    }
    float2* dst = (dst_sel == 0) ? g_a1024 : ((dst_sel == 1) ? g_b1024 : g_nr1024);
    float4* ob = (float4*)(dst + (size_t)b * HW2 + (size_t)yy * W2 + 4 * xq);
    ob[0] = make_float4(2.f * ox[0], 2.f * oy[0], 2.f * ox[1], 2.f * oy[1]);
    ob[1] = make_float4(2.f * ox[2], 2.f * oy[2], 2.f * ox[3], 2.f * oy[3]);
}

// -------- fused: reg gather tables -> 4ch-at-a-time warp+downsample --------
__global__ void __launch_bounds__(256) k_warpdown(
        float* __restrict__ out, int field_sel, int to_final) {
    __shared__ float4 s_w[TWNW];
    int b = blockIdx.z;
    int x0 = blockIdx.x * TSW, y0 = blockIdx.y * TSW;
    int gx0 = 2 * x0 - 1, gy0 = 2 * y0 - 1;
    int tid = threadIdx.x;

    const float2* fld = ((field_sel == 0) ? g_a1024 : g_nr1024) + (size_t)b * HW2;

    float4   rw[NPOS];
    unsigned rpk[NPOS];
    #pragma unroll
    for (int k = 0; k < NPOS; k++) {
        int i = tid + 256 * k;
        if (i < TWNW) {
            int r = i / TWW, cc = i - r * TWW;
            int Y = min(max(gy0 + r, 0), H2 - 1);
            int X = min(max(gx0 + cc, 0), W2 - 1);
            float2 f = fld[Y * W2 + X];
            float sx = (float)(gx0 + cc) + f.x;
            float sy = (float)(gy0 + r) + f.y;
            float xf = floorf(sx), yf = floorf(sy);
            float fx = sx - xf, fy = sy - yf;
            int ix0 = (int)xf, iy0 = (int)yf;
            bool bx0 = (unsigned)ix0 < W2, bx1 = (unsigned)(ix0 + 1) < W2;
            bool by0 = (unsigned)iy0 < H2, by1 = (unsigned)(iy0 + 1) < H2;
            float wx0 = bx0 ? (1.f - fx) : 0.f, wx1 = bx1 ? fx : 0.f;
            float wy0 = by0 ? (1.f - fy) : 0.f, wy1 = by1 ? fy : 0.f;
            rw[k] = make_float4(wy0 * wx0, wy0 * wx1, wy1 * wx0, wy1 * wx1);
            int cx0 = min(max(ix0, 0), W2 - 1), cx1 = min(max(ix0 + 1, 0), W2 - 1);
            int cy0 = min(max(iy0, 0), H2 - 1), cy1 = min(max(iy0 + 1, 0), H2 - 1);
            rpk[k] = (unsigned)(cy0 * W2 + cx0)
                   | ((unsigned)(cx1 - cx0) << 20)
                   | ((unsigned)(cy1 - cy0) << 21);
        }
    }

    const float4* img = g_up16 + (size_t)b * NG * HW2;
    float* dstb = to_final ? (out + ((size_t)b * 2 * NF + NF) * HW)
                           : (g_warped + (size_t)b * NF * HW);
    int lx = tid & (TSW - 1), ly = tid >> 4;
    int yy = y0 + ly, xx = x0 + lx;
    float invsy = (yy == 0 || yy == HH - 1) ? (1.f / 1.75f) : 0.5f;
    float invsx = (xx == 0 || xx == WW - 1) ? (1.f / 1.75f) : 0.5f;
    float wyv[4], wxv[4];
    #pragma unroll
    for (int t = 0; t < 4; t++) {
        wyv[t] = ((unsigned)(gy0 + 2 * ly + t) < H2) ? dbase(t) * invsy : 0.f;
        wxv[t] = ((unsigned)(gx0 + 2 * lx + t) < W2) ? dbase(t) * invsx : 0.f;
    }
    int sbase = (2 * ly) * TWW + 2 * lx;
    int opix = yy * WW + xx;

    for (int g = 0; g < NG; g++) {
        const float4* p = img + (size_t)g * HW2;
        #pragma unroll
        for (int k = 0; k < NPOS; k++) {
            int i = tid + 256 * k;
            if (i < TWNW) {
                unsigned pk = rpk[k];
                float4 w = rw[k];
                int o00 = (int)(pk & 0xFFFFFu);
                int dx  = (int)((pk >> 20) & 1u);
                int o10 = o00 + (int)((pk >> 11) & 1024u);
                float4 v00 = p[o00], v01 = p[o00 + dx];
                float4 v10 = p[o10], v11 = p[o10 + dx];
                float4 acc;
                acc.x = w.x * v00.x + w.y * v01.x + w.z * v10.x + w.w * v11.x;
                acc.y = w.x * v00.y + w.y * v01.y + w.z * v10.y + w.w * v11.y;
                acc.z = w.x * v00.z + w.y * v01.z + w.z * v10.z + w.w * v11.z;
                acc.w = w.x * v00.w + w.y * v01.w + w.z * v10.w + w.w * v11.w;
                s_w[i] = acc;
            }
        }
        __syncthreads();
        float4 acc = make_float4(0.f, 0.f, 0.f, 0.f);
        #pragma unroll
        for (int ty = 0; ty < 4; ty++) {
            const float4* sr = s_w + sbase + ty * TWW;
            float4 rowv = make_float4(0.f, 0.f, 0.f, 0.f);
            #pragma unroll
            for (int tx = 0; tx < 4; tx++) {
                float4 v = sr[tx];
                float w = wxv[tx];
                rowv.x += w * v.x; rowv.y += w * v.y;
                rowv.z += w * v.z; rowv.w += w * v.w;
            }
            float w = wyv[ty];
            acc.x += w * rowv.x; acc.y += w * rowv.y;
            acc.z += w * rowv.z; acc.w += w * rowv.w;
        }
        dstb[(size_t)(4 * g + 0) * HW + opix] = acc.x;
        dstb[(size_t)(4 * g + 1) * HW + opix] = acc.y;
        dstb[(size_t)(4 * g + 2) * HW + opix] = acc.z;
        dstb[(size_t)(4 * g + 3) * HW + opix] = acc.w;
        __syncthreads();
    }
}

// -------- 3x3 conv 50->2: smem-tiled 32x32, per-channel staging ---------------
// thread = column lx of the tile, 4 output rows; stencil served from smem.
__global__ void __launch_bounds__(256) k_conv(
        const float* __restrict__ x, const float* __restrict__ res,
        const float* __restrict__ Wc, const float* __restrict__ bias,
        float* __restrict__ out) {
    __shared__ float sw[2 * CINc * 9];
    __shared__ float tile[CTW * CTP];
    int tid = threadIdx.x;
    for (int i = tid; i < 2 * CINc * 9; i += 256) sw[i] = Wc[i];

    int b = blockIdx.z;
    int x0 = blockIdx.x * CTS, y0 = blockIdx.y * CTS;
    int lx = tid & 31, ly4 = tid >> 5;      // 8 thread-rows x 4 output rows each

    const float* xb = x + (size_t)b * 2 * NF * HW;
    const float* wb = g_warped + (size_t)b * NF * HW;
    const float* rb = res + (size_t)b * 2 * HW;

    float a0[4] = {0.f, 0.f, 0.f, 0.f};
    float a1[4] = {0.f, 0.f, 0.f, 0.f};

    #pragma unroll 1
    for (int c = 0; c < CINc; c++) {
        const float* p = (c < 32) ? (xb + (size_t)c * HW)
                       : (c < 48) ? (wb + (size_t)(c - 32) * HW)
                                  : (rb + (size_t)(c - 48) * HW);
        // stage 34x34 halo tile (zero-padded at image edges)
        #pragma unroll
        for (int k = 0; k < 5; k++) {
            int i = tid + 256 * k;
            if (i < CTW * CTW) {
                int r = i / CTW, col = i - r * CTW;
                int gy = y0 - 1 + r, gx = x0 - 1 + col;
                float v = 0.f;
                if ((unsigned)gy < HH && (unsigned)gx < WW) v = p[gy * WW + gx];
                tile[r * CTP + col] = v;
            }
        }
        __syncthreads();

        const float* q = sw + c * 9;
        const float* u = sw + CINc * 9 + c * 9;
        float q0 = q[0], q1 = q[1], q2 = q[2], q3 = q[3], q4 = q[4];
        float q5 = q[5], q6 = q[6], q7 = q[7], q8 = q[8];
        float u0 = u[0], u1 = u[1], u2 = u[2], u3 = u[3], u4 = u[4];
        float u5 = u[5], u6 = u[6], u7 = u[7], u8 = u[8];

        // 6 tile rows x 3 cols feed 4 output rows
        float v[6][3];
        int base = (ly4 * 4) * CTP + lx;
        #pragma unroll
        for (int r6 = 0; r6 < 6; r6++) {
            v[r6][0] = tile[base + r6 * CTP];
            v[r6][1] = tile[base + r6 * CTP + 1];
            v[r6][2] = tile[base + r6 * CTP + 2];
        }
        #pragma unroll
        for (int k = 0; k < 4; k++) {
            a0[k] += v[k][0] * q0 + v[k][1] * q1 + v[k][2] * q2
                   + v[k+1][0] * q3 + v[k+1][1] * q4 + v[k+1][2] * q5
                   + v[k+2][0] * q6 + v[k+2][1] * q7 + v[k+2][2] * q8;
            a1[k] += v[k][0] * u0 + v[k][1] * u1 + v[k][2] * u2
                   + v[k+1][0] * u3 + v[k+1][1] * u4 + v[k+1][2] * u5
                   + v[k+2][0] * u6 + v[k+2][1] * u7 + v[k+2][2] * u8;
        }
        __syncthreads();
    }

    float b0 = bias[0], b1 = bias[1];
    float* o = g_adj + (size_t)b * 2 * HW;
    float* ob = out + (size_t)b * 2 * NF * HW;
    #pragma unroll
    for (int k = 0; k < 4; k++) {
        int pc = (y0 + ly4 * 4 + k) * WW + x0 + lx;
        o[pc]      = a0[k] + b0;
        o[HW + pc] = a1[k] + b1;
        // pass-through: out[b][0..15] = x[b][0..15]
        #pragma unroll
        for (int c = 0; c < NF; c++)
            ob[(size_t)c * HW + pc] = xb[(size_t)c * HW + pc];
    }
}

// -------- fused: warp a1024 by b1024 (tables) -> downsample*0.5 + adj ----------
__global__ void __launch_bounds__(256) k_combine() {
    __shared__ float2 s_w[TWNW];
    int b = blockIdx.z;
    int x0 = blockIdx.x * TSW, y0 = blockIdx.y * TSW;
    int gx0 = 2 * x0 - 1, gy0 = 2 * y0 - 1;
    int tid = threadIdx.x;

    const float2* bf = g_b1024 + (size_t)b * HW2;
    const float2* af = g_a1024 + (size_t)b * HW2;

    #pragma unroll
    for (int k = 0; k < NPOS; k++) {
        int i = tid + 256 * k;
        if (i < TWNW) {
            int r = i / TWW, cc = i - r * TWW;
            int Y = min(max(gy0 + r, 0), H2 - 1);
            int X = min(max(gx0 + cc, 0), W2 - 1);
            float2 f = bf[Y * W2 + X];
            float sx = (float)(gx0 + cc) + f.x;
            float sy = (float)(gy0 + r) + f.y;
            float xf = floorf(sx), yf = floorf(sy);
            float fx = sx - xf, fy = sy - yf;
            int ix0 = (int)xf, iy0 = (int)yf;
            bool bx0 = (unsigned)ix0 < W2, bx1 = (unsigned)(ix0 + 1) < W2;
            bool by0 = (unsigned)iy0 < H2, by1 = (unsigned)(iy0 + 1) < H2;
            float wx0 = bx0 ? (1.f - fx) : 0.f, wx1 = bx1 ? fx : 0.f;
            float wy0 = by0 ? (1.f - fy) : 0.f, wy1 = by1 ? fy : 0.f;
            float w00 = wy0 * wx0, w01 = wy0 * wx1, w10 = wy1 * wx0, w11 = wy1 * wx1;
            int cx0 = min(max(ix0, 0), W2 - 1), cx1 = min(max(ix0 + 1, 0), W2 - 1);
            int cy0 = min(max(iy0, 0), H2 - 1), cy1 = min(max(iy0 + 1, 0), H2 - 1);
            int o00 = cy0 * W2 + cx0;
            int dxo = cx1 - cx0;
            int o10 = o00 + (cy1 - cy0) * W2;
            float2 v00 = af[o00], v01 = af[o00 + dxo];
            float2 v10 = af[o10], v11 = af[o10 + dxo];
            s_w[i] = make_float2(
                w00 * v00.x + w01 * v01.x + w10 * v10.x + w11 * v11.x,
                w00 * v00.y + w01 * v01.y + w10 * v10.y + w11 * v11.y);
        }
    }
    __syncthreads();

    int lx = tid & (TSW - 1), ly = tid >> 4;
    int yy = y0 + ly, xx = x0 + lx;
    float invsy = (yy == 0 || yy == HH - 1) ? (1.f / 1.75f) : 0.5f;
    float invsx = (xx == 0 || xx == WW - 1) ? (1.f / 1.75f) : 0.5f;
    float wyv[4], wxv[4];
    #pragma unroll
    for (int t = 0; t < 4; t++) {
        wyv[t] = ((unsigned)(gy0 + 2 * ly + t) < H2) ? dbase(t) * invsy : 0.f;
        wxv[t] = ((unsigned)(gx0 + 2 * lx + t) < W2) ? dbase(t) * invsx : 0.f;
    }
    int sbase = (2 * ly) * TWW + 2 * lx;
    float accx = 0.f, accy = 0.f;
    #pragma unroll
    for (int ty = 0; ty < 4; ty++) {
        const float2* sr = s_w + sbase + ty * TWW;
        float rx = wxv[0] * sr[0].x + wxv[1] * sr[1].x + wxv[2] * sr[2].x + wxv[3] * sr[3].x;
        float ry = wxv[0] * sr[0].y + wxv[1] * sr[1].y + wxv[2] * sr[2].y + wxv[3] * sr[3].y;
        accx += wyv[ty] * rx;
        accy += wyv[ty] * ry;
    }
    int p = yy * WW + xx;
    const float* ad = g_adj + (size_t)b * 2 * HW;
    float* nr = g_newres + (size_t)b * 2 * HW;
    nr[p]      = ad[p]      + 0.5f * accx;
    nr[HW + p] = ad[HW + p] + 0.5f * accy;
}

// -------- launch --------
extern "C" void kernel_launch(void* const* d_in, const int* in_sizes, int n_in,
                              void* d_out, int out_size) {
    const float* x    = (const float*)d_in[0];
    const float* res  = (const float*)d_in[1];
    const float* Wc   = (const float*)d_in[2];
    const float* bias = (const float*)d_in[3];
    float* out = (float*)d_out;

    const int T = 256;
    dim3 gu1((BB * HW2 + T - 1) / T);
    dim3 gu((BB * H2 * (W2 / 4) + T - 1) / T);
    dim3 gcv(WW / CTS, HH / CTS, BB);   // 16 x 16 x 2 conv tiles
    dim3 gw(HH / TSW, WW / TSW, BB);

    k_up_img<<<gu1, T>>>(x);                      // tgt -> g_up16 (packed x4)
    k_up_res<<<gu, T>>>(res, 0, 0);               // res -> g_a1024 (*2)
    k_warpdown<<<gw, T>>>(nullptr, 0, 0);         // warp by a1024 -> g_warped
    k_conv<<<gcv, T>>>(x, res, Wc, bias, out);    // adj + src pass-through
    k_up_res<<<gu, T>>>(nullptr, 1, 1);           // adj -> g_b1024 (*2)
    k_combine<<<gw, T>>>();                       // -> g_newres
    k_up_res<<<gu, T>>>(nullptr, 2, 2);           // new_res -> g_nr1024 (*2)
    k_warpdown<<<gw, T>>>(out, 1, 1);             // warp by nr1024 -> out[16..31]
}

// round 11
// speedup vs baseline: 1.0952x; 1.0422x over previous
#include <cuda_runtime.h>

#define BB 2
#define NF 16
#define NG 4               // channel groups of 4 (float4)
#define HH 512
#define WW 512
#define H2 1024
#define W2 1024
#define CINc 50
#define HW (HH*WW)
#define HW2 (H2*W2)

// warp/combine tiles: 16x16 outputs at 512-res
#define TSW 16
#define TWW 34             // 2*TSW+2
#define TWNW (TWW*TWW)     // 1156
#define NPOS 5             // ceil(TWNW/256)

// conv tile
#define CTS 32             // 32x32 outputs per block
#define CTW 34             // with halo
#define CTP 36             // padded smem row stride
#define CNL 5              // staging loads per thread: ceil(34*34/256)

// -------- scratch (device globals; referenced ONLY from device code) --------
__device__ float4 g_up16 [(size_t)BB*NG*HW2];  // upsampled tgt, channel-packed x4
__device__ float  g_warped[(size_t)BB*NF*HW];  // warped tgt @512, planar
__device__ float  g_adj  [(size_t)BB*2*HW];    // conv output, planar
__device__ float  g_newres[(size_t)BB*2*HW];   // combined residual, planar
__device__ float2 g_a1024[(size_t)BB*HW2];     // up(res)*2, interleaved
__device__ float2 g_b1024[(size_t)BB*HW2];     // up(adj)*2
__device__ float2 g_nr1024[(size_t)BB*HW2];    // up(new_res)*2

// -------- resize helpers (jax.image.resize bilinear; validated R1) --------
__device__ __forceinline__ void up_taps(int i, int n_in, int& t0, int& t1,
                                        float& w0, float& w1) {
    int k = i >> 1;
    if ((i & 1) == 0) { t0 = k - 1; t1 = k;     w0 = 0.25f; w1 = 0.75f; }
    else              { t0 = k;     t1 = k + 1; w0 = 0.75f; w1 = 0.25f; }
    if (t0 < 0)     { t0 = t1; w0 = 0.f; w1 = 1.f; }
    if (t1 >= n_in) { t1 = t0; w1 = 0.f; w0 = 1.f; }
}
__device__ __forceinline__ float dbase(int t) { return (t == 0 || t == 3) ? 0.25f : 0.75f; }

// -------- kernel 1: upsample tgt 512->1024 into channel-packed float4 --------
__global__ void __launch_bounds__(256) k_up_img(const float* __restrict__ x) {
    int idx = blockIdx.x * blockDim.x + threadIdx.x;
    if (idx >= BB * HW2) return;
    int xx = idx & (W2 - 1), yy = (idx >> 10) & (H2 - 1), b = idx >> 20;
    int ty0, ty1, tx0, tx1; float wy0, wy1, wx0, wx1;
    up_taps(yy, HH, ty0, ty1, wy0, wy1);
    up_taps(xx, WW, tx0, tx1, wx0, wx1);
    int r0 = ty0 * WW, r1 = ty1 * WW;
    float w00 = wy0 * wx0, w01 = wy0 * wx1, w10 = wy1 * wx0, w11 = wy1 * wx1;

    const float* xb = x + ((size_t)b * 2 * NF + NF) * HW;
    float4* ob = g_up16 + (size_t)b * NG * HW2 + (size_t)yy * W2 + xx;
    #pragma unroll
    for (int g = 0; g < NG; g++) {
        float4 o;
        float* oo = (float*)&o;
        #pragma unroll
        for (int j = 0; j < 4; j++) {
            const float* p = xb + (size_t)(4 * g + j) * HW;
            oo[j] = w00 * p[r0 + tx0] + w01 * p[r0 + tx1]
                  + w10 * p[r1 + tx0] + w11 * p[r1 + tx1];
        }
        ob[(size_t)g * HW2] = o;
    }
}

// -------- kernel 2: upsample a 2ch 512 field ->1024, *2, interleaved float2 ----
__global__ void __launch_bounds__(256) k_up_res(const float* __restrict__ ext,
                                                int src_sel, int dst_sel) {
    int idx = blockIdx.x * blockDim.x + threadIdx.x;
    if (idx >= BB * H2 * (W2 / 4)) return;
    int xq = idx & (W2 / 4 - 1);
    int yy = (idx >> 8) & (H2 - 1);
    int b  = idx >> 18;
    int m = 2 * xq;
    int mm1 = max(m - 1, 0), mp2 = min(m + 2, WW - 1);
    float a00 = (m == 0) ? 0.f : 0.25f,  a01 = (m == 0) ? 1.f : 0.75f;
    float a30 = (m == WW - 2) ? 1.f : 0.75f, a31 = (m == WW - 2) ? 0.f : 0.25f;
    int ty0, ty1; float wy0, wy1;
    up_taps(yy, HH, ty0, ty1, wy0, wy1);
    int r0 = ty0 * WW, r1 = ty1 * WW;

    const float* src = (src_sel == 0) ? ext : ((src_sel == 1) ? g_adj : g_newres);
    const float* p0 = src + (size_t)b * 2 * HW;
    const float* p1 = p0 + HW;
    float ox[4], oy[4];
    {
        float s0 = p0[r0 + mm1]   * wy0 + p0[r1 + mm1]   * wy1;
        float s1 = p0[r0 + m]     * wy0 + p0[r1 + m]     * wy1;
        float s2 = p0[r0 + m + 1] * wy0 + p0[r1 + m + 1] * wy1;
        float s3 = p0[r0 + mp2]   * wy0 + p0[r1 + mp2]   * wy1;
        ox[0] = a00 * s0 + a01 * s1;  ox[1] = 0.75f * s1 + 0.25f * s2;
        ox[2] = 0.25f * s1 + 0.75f * s2;  ox[3] = a30 * s2 + a31 * s3;
    }
    {
        float s0 = p1[r0 + mm1]   * wy0 + p1[r1 + mm1]   * wy1;
        float s1 = p1[r0 + m]     * wy0 + p1[r1 + m]     * wy1;
        float s2 = p1[r0 + m + 1] * wy0 + p1[r1 + m + 1] * wy1;
        float s3 = p1[r0 + mp2]   * wy0 + p1[r1 + mp2]   * wy1;
        oy[0] = a00 * s0 + a01 * s1;  oy[1] = 0.75f * s1 + 0.25f * s2;
        oy[2] = 0.25f * s1 + 0.75f * s2;  oy[3] = a30 * s2 + a31 * s3;
    }
    float2* dst = (dst_sel == 0) ? g_a1024 : ((dst_sel == 1) ? g_b1024 : g_nr1024);
    float4* ob = (float4*)(dst + (size_t)b * HW2 + (size_t)yy * W2 + 4 * xq);
    ob[0] = make_float4(2.f * ox[0], 2.f * oy[0], 2.f * ox[1], 2.f * oy[1]);
    ob[1] = make_float4(2.f * ox[2], 2.f * oy[2], 2.f * ox[3], 2.f * oy[3]);
}

// -------- fused: reg gather tables -> 4ch-at-a-time warp+downsample --------
__global__ void __launch_bounds__(256) k_warpdown(
        float* __restrict__ out, int field_sel, int to_final) {
    __shared__ float4 s_w[TWNW];
    int b = blockIdx.z;
    int x0 = blockIdx.x * TSW, y0 = blockIdx.y * TSW;
    int gx0 = 2 * x0 - 1, gy0 = 2 * y0 - 1;
    int tid = threadIdx.x;

    const float2* fld = ((field_sel == 0) ? g_a1024 : g_nr1024) + (size_t)b * HW2;

    float4   rw[NPOS];
    unsigned rpk[NPOS];
    #pragma unroll
    for (int k = 0; k < NPOS; k++) {
        int i = tid + 256 * k;
        if (i < TWNW) {
            int r = i / TWW, cc = i - r * TWW;
            int Y = min(max(gy0 + r, 0), H2 - 1);
            int X = min(max(gx0 + cc, 0), W2 - 1);
            float2 f = fld[Y * W2 + X];
            float sx = (float)(gx0 + cc) + f.x;
            float sy = (float)(gy0 + r) + f.y;
            float xf = floorf(sx), yf = floorf(sy);
            float fx = sx - xf, fy = sy - yf;
            int ix0 = (int)xf, iy0 = (int)yf;
            bool bx0 = (unsigned)ix0 < W2, bx1 = (unsigned)(ix0 + 1) < W2;
            bool by0 = (unsigned)iy0 < H2, by1 = (unsigned)(iy0 + 1) < H2;
            float wx0 = bx0 ? (1.f - fx) : 0.f, wx1 = bx1 ? fx : 0.f;
            float wy0 = by0 ? (1.f - fy) : 0.f, wy1 = by1 ? fy : 0.f;
            rw[k] = make_float4(wy0 * wx0, wy0 * wx1, wy1 * wx0, wy1 * wx1);
            int cx0 = min(max(ix0, 0), W2 - 1), cx1 = min(max(ix0 + 1, 0), W2 - 1);
            int cy0 = min(max(iy0, 0), H2 - 1), cy1 = min(max(iy0 + 1, 0), H2 - 1);
            rpk[k] = (unsigned)(cy0 * W2 + cx0)
                   | ((unsigned)(cx1 - cx0) << 20)
                   | ((unsigned)(cy1 - cy0) << 21);
        }
    }

    const float4* img = g_up16 + (size_t)b * NG * HW2;
    float* dstb = to_final ? (out + ((size_t)b * 2 * NF + NF) * HW)
                           : (g_warped + (size_t)b * NF * HW);
    int lx = tid & (TSW - 1), ly = tid >> 4;
    int yy = y0 + ly, xx = x0 + lx;
    float invsy = (yy == 0 || yy == HH - 1) ? (1.f / 1.75f) : 0.5f;
    float invsx = (xx == 0 || xx == WW - 1) ? (1.f / 1.75f) : 0.5f;
    float wyv[4], wxv[4];
    #pragma unroll
    for (int t = 0; t < 4; t++) {
        wyv[t] = ((unsigned)(gy0 + 2 * ly + t) < H2) ? dbase(t) * invsy : 0.f;
        wxv[t] = ((unsigned)(gx0 + 2 * lx + t) < W2) ? dbase(t) * invsx : 0.f;
    }
    int sbase = (2 * ly) * TWW + 2 * lx;
    int opix = yy * WW + xx;

    for (int g = 0; g < NG; g++) {
        const float4* p = img + (size_t)g * HW2;
        #pragma unroll
        for (int k = 0; k < NPOS; k++) {
            int i = tid + 256 * k;
            if (i < TWNW) {
                unsigned pk = rpk[k];
                float4 w = rw[k];
                int o00 = (int)(pk & 0xFFFFFu);
                int dx  = (int)((pk >> 20) & 1u);
                int o10 = o00 + (int)((pk >> 11) & 1024u);
                float4 v00 = p[o00], v01 = p[o00 + dx];
                float4 v10 = p[o10], v11 = p[o10 + dx];
                float4 acc;
                acc.x = w.x * v00.x + w.y * v01.x + w.z * v10.x + w.w * v11.x;
                acc.y = w.x * v00.y + w.y * v01.y + w.z * v10.y + w.w * v11.y;
                acc.z = w.x * v00.z + w.y * v01.z + w.z * v10.z + w.w * v11.z;
                acc.w = w.x * v00.w + w.y * v01.w + w.z * v10.w + w.w * v11.w;
                s_w[i] = acc;
            }
        }
        __syncthreads();
        float4 acc = make_float4(0.f, 0.f, 0.f, 0.f);
        #pragma unroll
        for (int ty = 0; ty < 4; ty++) {
            const float4* sr = s_w + sbase + ty * TWW;
            float4 rowv = make_float4(0.f, 0.f, 0.f, 0.f);
            #pragma unroll
            for (int tx = 0; tx < 4; tx++) {
                float4 v = sr[tx];
                float w = wxv[tx];
                rowv.x += w * v.x; rowv.y += w * v.y;
                rowv.z += w * v.z; rowv.w += w * v.w;
            }
            float w = wyv[ty];
            acc.x += w * rowv.x; acc.y += w * rowv.y;
            acc.z += w * rowv.z; acc.w += w * rowv.w;
        }
        dstb[(size_t)(4 * g + 0) * HW + opix] = acc.x;
        dstb[(size_t)(4 * g + 1) * HW + opix] = acc.y;
        dstb[(size_t)(4 * g + 2) * HW + opix] = acc.z;
        dstb[(size_t)(4 * g + 3) * HW + opix] = acc.w;
        __syncthreads();
    }
}

// -------- 3x3 conv 50->2: smem-tiled 32x32, DOUBLE-BUFFERED channel pipeline ---
__global__ void __launch_bounds__(256) k_conv(
        const float* __restrict__ x, const float* __restrict__ res,
        const float* __restrict__ Wc, const float* __restrict__ bias,
        float* __restrict__ out) {
    __shared__ float sw[2 * CINc * 9];
    __shared__ float tile[2][CTW * CTP];
    int tid = threadIdx.x;
    for (int i = tid; i < 2 * CINc * 9; i += 256) sw[i] = Wc[i];

    int b = blockIdx.z;
    int x0 = blockIdx.x * CTS, y0 = blockIdx.y * CTS;
    int lx = tid & 31, ly4 = tid >> 5;

    const float* xb = x + (size_t)b * 2 * NF * HW;
    const float* wb = g_warped + (size_t)b * NF * HW;
    const float* rb = res + (size_t)b * 2 * HW;

    // hoisted staging geometry: smem slot + gmem offset + validity per k
    int  sofs[CNL], gofs[CNL];
    bool inb[CNL];
    #pragma unroll
    for (int k = 0; k < CNL; k++) {
        int i = tid + 256 * k;
        bool valid = (i < CTW * CTW);
        int r = i / CTW, col = i - r * CTW;
        int gy = y0 - 1 + r, gx = x0 - 1 + col;
        inb[k]  = valid && ((unsigned)gy < HH) && ((unsigned)gx < WW);
        sofs[k] = valid ? (r * CTP + col) : 0;
        gofs[k] = inb[k] ? (gy * WW + gx) : 0;
        if (!valid) sofs[k] = -1;
    }

    float a0[4] = {0.f, 0.f, 0.f, 0.f};
    float a1[4] = {0.f, 0.f, 0.f, 0.f};

    const float* pc0 = xb;   // channel 0 pointer
    float ld[CNL];
    #pragma unroll
    for (int k = 0; k < CNL; k++) ld[k] = inb[k] ? pc0[gofs[k]] : 0.f;
    #pragma unroll
    for (int k = 0; k < CNL; k++) if (sofs[k] >= 0) tile[0][sofs[k]] = ld[k];
    __syncthreads();

    int base = (ly4 * 4) * CTP + lx;

    #pragma unroll 1
    for (int c = 0; c < CINc; c++) {
        // prefetch channel c+1 into registers (overlaps with compute below)
        if (c + 1 < CINc) {
            int cn = c + 1;
            const float* p = (cn < 32) ? (xb + (size_t)cn * HW)
                           : (cn < 48) ? (wb + (size_t)(cn - 32) * HW)
                                       : (rb + (size_t)(cn - 48) * HW);
            #pragma unroll
            for (int k = 0; k < CNL; k++) ld[k] = inb[k] ? p[gofs[k]] : 0.f;
        }

        // compute channel c from tile[c&1]
        const float* tl = tile[c & 1];
        const float* q = sw + c * 9;
        const float* u = sw + CINc * 9 + c * 9;
        float q0 = q[0], q1 = q[1], q2 = q[2], q3 = q[3], q4 = q[4];
        float q5 = q[5], q6 = q[6], q7 = q[7], q8 = q[8];
        float u0 = u[0], u1 = u[1], u2 = u[2], u3 = u[3], u4 = u[4];
        float u5 = u[5], u6 = u[6], u7 = u[7], u8 = u[8];
        float v[6][3];
        #pragma unroll
        for (int r6 = 0; r6 < 6; r6++) {
            v[r6][0] = tl[base + r6 * CTP];
            v[r6][1] = tl[base + r6 * CTP + 1];
            v[r6][2] = tl[base + r6 * CTP + 2];
        }
        #pragma unroll
        for (int k = 0; k < 4; k++) {
            a0[k] += v[k][0] * q0 + v[k][1] * q1 + v[k][2] * q2
                   + v[k+1][0] * q3 + v[k+1][1] * q4 + v[k+1][2] * q5
                   + v[k+2][0] * q6 + v[k+2][1] * q7 + v[k+2][2] * q8;
            a1[k] += v[k][0] * u0 + v[k][1] * u1 + v[k][2] * u2
                   + v[k+1][0] * u3 + v[k+1][1] * u4 + v[k+1][2] * u5
                   + v[k+2][0] * u6 + v[k+2][1] * u7 + v[k+2][2] * u8;
        }

        // store prefetched channel to the other buffer, then one sync
        if (c + 1 < CINc) {
            float* tn = tile[(c + 1) & 1];
            #pragma unroll
            for (int k = 0; k < CNL; k++) if (sofs[k] >= 0) tn[sofs[k]] = ld[k];
        }
        __syncthreads();
    }

    float b0 = bias[0], b1 = bias[1];
    float* o = g_adj + (size_t)b * 2 * HW;
    float* ob = out + (size_t)b * 2 * NF * HW;
    #pragma unroll
    for (int k = 0; k < 4; k++) {
        int pc = (y0 + ly4 * 4 + k) * WW + x0 + lx;
        o[pc]      = a0[k] + b0;
        o[HW + pc] = a1[k] + b1;
        // pass-through: out[b][0..15] = x[b][0..15]
        #pragma unroll
        for (int c = 0; c < NF; c++)
            ob[(size_t)c * HW + pc] = xb[(size_t)c * HW + pc];
    }
}

// -------- fused: warp a1024 by b1024 (tables) -> downsample*0.5 + adj ----------
__global__ void __launch_bounds__(256) k_combine() {
    __shared__ float2 s_w[TWNW];
    int b = blockIdx.z;
    int x0 = blockIdx.x * TSW, y0 = blockIdx.y * TSW;
    int gx0 = 2 * x0 - 1, gy0 = 2 * y0 - 1;
    int tid = threadIdx.x;

    const float2* bf = g_b1024 + (size_t)b * HW2;
    const float2* af = g_a1024 + (size_t)b * HW2;

    #pragma unroll
    for (int k = 0; k < NPOS; k++) {
        int i = tid + 256 * k;
        if (i < TWNW) {
            int r = i / TWW, cc = i - r * TWW;
            int Y = min(max(gy0 + r, 0), H2 - 1);
            int X = min(max(gx0 + cc, 0), W2 - 1);
            float2 f = bf[Y * W2 + X];
            float sx = (float)(gx0 + cc) + f.x;
            float sy = (float)(gy0 + r) + f.y;
            float xf = floorf(sx), yf = floorf(sy);
            float fx = sx - xf, fy = sy - yf;
            int ix0 = (int)xf, iy0 = (int)yf;
            bool bx0 = (unsigned)ix0 < W2, bx1 = (unsigned)(ix0 + 1) < W2;
            bool by0 = (unsigned)iy0 < H2, by1 = (unsigned)(iy0 + 1) < H2;
            float wx0 = bx0 ? (1.f - fx) : 0.f, wx1 = bx1 ? fx : 0.f;
            float wy0 = by0 ? (1.f - fy) : 0.f, wy1 = by1 ? fy : 0.f;
            float w00 = wy0 * wx0, w01 = wy0 * wx1, w10 = wy1 * wx0, w11 = wy1 * wx1;
            int cx0 = min(max(ix0, 0), W2 - 1), cx1 = min(max(ix0 + 1, 0), W2 - 1);
            int cy0 = min(max(iy0, 0), H2 - 1), cy1 = min(max(iy0 + 1, 0), H2 - 1);
            int o00 = cy0 * W2 + cx0;
            int dxo = cx1 - cx0;
            int o10 = o00 + (cy1 - cy0) * W2;
            float2 v00 = af[o00], v01 = af[o00 + dxo];
            float2 v10 = af[o10], v11 = af[o10 + dxo];
            s_w[i] = make_float2(
                w00 * v00.x + w01 * v01.x + w10 * v10.x + w11 * v11.x,
                w00 * v00.y + w01 * v01.y + w10 * v10.y + w11 * v11.y);
        }
    }
    __syncthreads();

    int lx = tid & (TSW - 1), ly = tid >> 4;
    int yy = y0 + ly, xx = x0 + lx;
    float invsy = (yy == 0 || yy == HH - 1) ? (1.f / 1.75f) : 0.5f;
    float invsx = (xx == 0 || xx == WW - 1) ? (1.f / 1.75f) : 0.5f;
    float wyv[4], wxv[4];
    #pragma unroll
    for (int t = 0; t < 4; t++) {
        wyv[t] = ((unsigned)(gy0 + 2 * ly + t) < H2) ? dbase(t) * invsy : 0.f;
        wxv[t] = ((unsigned)(gx0 + 2 * lx + t) < W2) ? dbase(t) * invsx : 0.f;
    }
    int sbase = (2 * ly) * TWW + 2 * lx;
    float accx = 0.f, accy = 0.f;
    #pragma unroll
    for (int ty = 0; ty < 4; ty++) {
        const float2* sr = s_w + sbase + ty * TWW;
        float rx = wxv[0] * sr[0].x + wxv[1] * sr[1].x + wxv[2] * sr[2].x + wxv[3] * sr[3].x;
        float ry = wxv[0] * sr[0].y + wxv[1] * sr[1].y + wxv[2] * sr[2].y + wxv[3] * sr[3].y;
        accx += wyv[ty] * rx;
        accy += wyv[ty] * ry;
    }
    int p = yy * WW + xx;
    const float* ad = g_adj + (size_t)b * 2 * HW;
    float* nr = g_newres + (size_t)b * 2 * HW;
    nr[p]      = ad[p]      + 0.5f * accx;
    nr[HW + p] = ad[HW + p] + 0.5f * accy;
}

// -------- launch --------
extern "C" void kernel_launch(void* const* d_in, const int* in_sizes, int n_in,
                              void* d_out, int out_size) {
    const float* x    = (const float*)d_in[0];
    const float* res  = (const float*)d_in[1];
    const float* Wc   = (const float*)d_in[2];
    const float* bias = (const float*)d_in[3];
    float* out = (float*)d_out;

    const int T = 256;
    dim3 gu1((BB * HW2 + T - 1) / T);
    dim3 gu((BB * H2 * (W2 / 4) + T - 1) / T);
    dim3 gcv(WW / CTS, HH / CTS, BB);   // 16 x 16 x 2 conv tiles
    dim3 gw(HH / TSW, WW / TSW, BB);

    k_up_img<<<gu1, T>>>(x);                      // tgt -> g_up16 (packed x4)
    k_up_res<<<gu, T>>>(res, 0, 0);               // res -> g_a1024 (*2)
    k_warpdown<<<gw, T>>>(nullptr, 0, 0);         // warp by a1024 -> g_warped
    k_conv<<<gcv, T>>>(x, res, Wc, bias, out);    // adj + src pass-through
    k_up_res<<<gu, T>>>(nullptr, 1, 1);           // adj -> g_b1024 (*2)
    k_combine<<<gw, T>>>();                       // -> g_newres
    k_up_res<<<gu, T>>>(nullptr, 2, 2);           // new_res -> g_nr1024 (*2)
    k_warpdown<<<gw, T>>>(out, 1, 1);             // warp by nr1024 -> out[16..31]
}